// round 8
// baseline (speedup 1.0000x reference)
#include <cuda_runtime.h>
#include <math.h>

#define NWIN     2048
#define NTOK     66
#define CDIM     256
#define NHEAD    8
#define HDIM     32
#define TOKN     2
#define NTHREADS 256

// shared memory layout (floats)
#define XS_OFF   0                   // Xs[66][260]
#define OS_OFF   (XS_OFF + 66*260)   // Os[66][260]
#define QS_OFF   (OS_OFF + 66*260)   // Q[66][33]
#define KS_OFF   (QS_OFF + 66*33)
#define VS_OFF   (KS_OFF + 66*33)
#define SS_OFF   (VS_OFF + 66*33)    // S[66][67]
#define WSH_OFF  (SS_OFF + 66*67)    // Wsh[32][97]
#define TB_OFF   (WSH_OFF + 32*97)   // bias table 225*8
#define BQ_OFF   (TB_OFF + 225*8)    // qkv_b 768
#define BP_OFF   (BQ_OFF + 768)      // proj_b 256
#define SMEM_FLOATS (BP_OFF + 256)
#define SMEM_BYTES  (SMEM_FLOATS * 4)

__device__ __forceinline__ float dot32(const float* __restrict__ a,
                                       const float* __restrict__ b) {
    float s = 0.f;
#pragma unroll
    for (int c = 0; c < 32; c++) s += a[c] * b[c];
    return s;
}

__global__ void __launch_bounds__(NTHREADS, 1)
win_attn_kernel(const float* __restrict__ x,
                const float* __restrict__ qkv_w,
                const float* __restrict__ qkv_b,
                const float* __restrict__ tab,
                const float* __restrict__ proj_w,
                const float* __restrict__ proj_b,
                float* __restrict__ out)
{
    extern __shared__ float sm[];
    float* Xs  = sm + XS_OFF;
    float* Os  = sm + OS_OFF;
    float* Qs  = sm + QS_OFF;
    float* Ks  = sm + KS_OFF;
    float* Vs  = sm + VS_OFF;
    float* Ss  = sm + SS_OFF;
    float* Wsh = sm + WSH_OFF;
    float* Tb  = sm + TB_OFF;
    float* Bq  = sm + BQ_OFF;
    float* Bp  = sm + BP_OFF;

    const int tid  = threadIdx.x;
    const int tx   = tid & 15;
    const int ty   = tid >> 4;
    const int warp = tid >> 5;
    const int lane = tid & 31;
    const int win  = blockIdx.x;
    const float scale = 0.17677669529663687f;  // 1/sqrt(32)

    // ---- stage inputs ----
    const float4* xg = (const float4*)(x + (size_t)win * NTOK * CDIM);
#pragma unroll 4
    for (int idx = tid; idx < NTOK * (CDIM / 4); idx += NTHREADS) {
        int n  = idx >> 6;        // /64
        int c4 = idx & 63;
        float4 v4 = xg[n * 64 + c4];
        *(float4*)(Xs + n * 260 + c4 * 4) = v4;
    }
    for (int idx = tid; idx < 225 * 8; idx += NTHREADS) Tb[idx] = tab[idx];
    for (int idx = tid; idx < 768; idx += NTHREADS)     Bq[idx] = qkv_b[idx];
    if (tid < 256) Bp[tid] = proj_b[tid];
    __syncthreads();

    // per-thread row set for GEMM phases (5 rows; last clamped, store-guarded)
    int rows[5];
    rows[0] = ty;      rows[1] = ty + 16; rows[2] = ty + 32; rows[3] = ty + 48;
    rows[4] = (ty < 2) ? (ty + 64) : 0;

    // =========================== per-head loop ===========================
    for (int h = 0; h < NHEAD; h++) {
        // ---- GEMM1: qkv_h[66][96] = Xs[66][256] @ W_h^T ----
        float acc[5][6];
#pragma unroll
        for (int i = 0; i < 5; i++)
#pragma unroll
            for (int j = 0; j < 6; j++) acc[i][j] = 0.f;

        const float* xb0 = Xs + rows[0] * 260;
        const float* xb1 = Xs + rows[1] * 260;
        const float* xb2 = Xs + rows[2] * 260;
        const float* xb3 = Xs + rows[3] * 260;
        const float* xb4 = Xs + rows[4] * 260;

        for (int kt = 0; kt < 256; kt += 32) {
            __syncthreads();
            // stage Wsh[c][o] transposed: o in [0,96), c in [0,32)
#pragma unroll
            for (int t = 0; t < 12; t++) {
                int idx = tid + t * NTHREADS;       // 3072 elems
                int o  = idx >> 5;
                int cc = idx & 31;
                int s  = o >> 5;
                int j  = o & 31;
                Wsh[cc * 97 + o] = qkv_w[(s * 256 + h * 32 + j) * 256 + kt + cc];
            }
            __syncthreads();
#pragma unroll
            for (int cc = 0; cc < 32; cc++) {
                float xr[5], wv[6];
                xr[0] = xb0[kt + cc]; xr[1] = xb1[kt + cc]; xr[2] = xb2[kt + cc];
                xr[3] = xb3[kt + cc]; xr[4] = xb4[kt + cc];
#pragma unroll
                for (int j = 0; j < 6; j++) wv[j] = Wsh[cc * 97 + tx * 6 + j];
#pragma unroll
                for (int i = 0; i < 5; i++)
#pragma unroll
                    for (int j = 0; j < 6; j++) acc[i][j] += xr[i] * wv[j];
            }
        }

        // store q (scaled) / k / v into smem
#pragma unroll
        for (int i = 0; i < 5; i++) {
            int row = ty + 16 * i;
            if (row < NTOK) {
#pragma unroll
                for (int j = 0; j < 6; j++) {
                    int col = tx * 6 + j;
                    int s = col >> 5, d = col & 31;
                    float val = acc[i][j] + Bq[s * 256 + h * 32 + d];
                    if (s == 0)      Qs[row * 33 + d] = val * scale;
                    else if (s == 1) Ks[row * 33 + d] = val;
                    else             Vs[row * 33 + d] = val;
                }
            }
        }
        __syncthreads();

        // ---- attention: warp per row ----
        for (int r = warp; r < NTOK; r += 8) {
            const float* qrow = Qs + r * 33;
            float v0 = dot32(qrow, Ks + lane * 33);
            float v1 = dot32(qrow, Ks + (lane + 32) * 33);
            float v2 = (lane < 2) ? dot32(qrow, Ks + (lane + 64) * 33)
                                  : -INFINITY;
            // relative position bias on spatial block
            if (r >= TOKN) {
                int p  = r - TOKN;
                int ph = p >> 3, pw = p & 7;
                if (lane >= TOKN) {
                    int qp = lane - TOKN;
                    int dy = ph - (qp >> 3) + 7, dx = pw - (qp & 7) + 7;
                    v0 += Tb[(dy * 15 + dx) * 8 + h];
                }
                {
                    int qp = lane + 32 - TOKN;
                    int dy = ph - (qp >> 3) + 7, dx = pw - (qp & 7) + 7;
                    v1 += Tb[(dy * 15 + dx) * 8 + h];
                }
                if (lane < 2) {
                    int qp = lane + 64 - TOKN;
                    int dy = ph - (qp >> 3) + 7, dx = pw - (qp & 7) + 7;
                    v2 += Tb[(dy * 15 + dx) * 8 + h];
                }
            }
            // softmax across the row (66 entries spread over lanes)
            float m = fmaxf(v0, fmaxf(v1, v2));
#pragma unroll
            for (int off = 16; off > 0; off >>= 1)
                m = fmaxf(m, __shfl_xor_sync(0xffffffffu, m, off));
            float e0 = __expf(v0 - m);
            float e1 = __expf(v1 - m);
            float e2 = (lane < 2) ? __expf(v2 - m) : 0.f;
            float s = e0 + e1 + e2;
#pragma unroll
            for (int off = 16; off > 0; off >>= 1)
                s += __shfl_xor_sync(0xffffffffu, s, off);
            float inv = __frcp_rn(s);
            Ss[r * 67 + lane]      = e0 * inv;
            Ss[r * 67 + lane + 32] = e1 * inv;
            if (lane < 2) Ss[r * 67 + lane + 64] = e2 * inv;
            __syncwarp();
            // P @ V  (lane = output dim d)
            float o = 0.f;
            const float* prow = Ss + r * 67;
#pragma unroll 6
            for (int j = 0; j < NTOK; j++) o += prow[j] * Vs[j * 33 + lane];
            Os[r * 260 + h * 32 + lane] = o;
        }
        __syncthreads();
    }

    // =========================== output proj ===========================
    const float* ob0 = Os + rows[0] * 260;
    const float* ob1 = Os + rows[1] * 260;
    const float* ob2 = Os + rows[2] * 260;
    const float* ob3 = Os + rows[3] * 260;
    const float* ob4 = Os + rows[4] * 260;

    for (int nb = 0; nb < 4; nb++) {
        float acc[5][4];
#pragma unroll
        for (int i = 0; i < 5; i++)
#pragma unroll
            for (int j = 0; j < 4; j++) acc[i][j] = 0.f;

        for (int kt = 0; kt < 256; kt += 32) {
            __syncthreads();
#pragma unroll
            for (int t = 0; t < 8; t++) {
                int idx = tid + t * NTHREADS;       // 2048 elems
                int o  = idx >> 5;
                int cc = idx & 31;
                Wsh[cc * 65 + o] = proj_w[(nb * 64 + o) * 256 + kt + cc];
            }
            __syncthreads();
#pragma unroll
            for (int cc = 0; cc < 32; cc++) {
                float ar[5], wv[4];
                ar[0] = ob0[kt + cc]; ar[1] = ob1[kt + cc]; ar[2] = ob2[kt + cc];
                ar[3] = ob3[kt + cc]; ar[4] = ob4[kt + cc];
#pragma unroll
                for (int j = 0; j < 4; j++) wv[j] = Wsh[cc * 65 + tx * 4 + j];
#pragma unroll
                for (int i = 0; i < 5; i++)
#pragma unroll
                    for (int j = 0; j < 4; j++) acc[i][j] += ar[i] * wv[j];
            }
        }
        // store with bias (vectorized, coalesced)
#pragma unroll
        for (int i = 0; i < 5; i++) {
            int row = ty + 16 * i;
            if (row < NTOK) {
                int col = nb * 64 + tx * 4;
                float4 o4;
                o4.x = acc[i][0] + Bp[col + 0];
                o4.y = acc[i][1] + Bp[col + 1];
                o4.z = acc[i][2] + Bp[col + 2];
                o4.w = acc[i][3] + Bp[col + 3];
                *(float4*)(out + ((size_t)win * NTOK + row) * CDIM + col) = o4;
            }
        }
    }
}

extern "C" void kernel_launch(void* const* d_in, const int* in_sizes, int n_in,
                              void* d_out, int out_size) {
    (void)in_sizes; (void)n_in; (void)out_size;
    const float* x      = (const float*)d_in[0];
    const float* qkv_w  = (const float*)d_in[1];
    const float* qkv_b  = (const float*)d_in[2];
    const float* tab    = (const float*)d_in[3];
    const float* proj_w = (const float*)d_in[4];
    const float* proj_b = (const float*)d_in[5];
    float* out = (float*)d_out;

    cudaFuncSetAttribute(win_attn_kernel,
                         cudaFuncAttributeMaxDynamicSharedMemorySize, SMEM_BYTES);
    win_attn_kernel<<<NWIN, NTHREADS, SMEM_BYTES>>>(
        x, qkv_w, qkv_b, tab, proj_w, proj_b, out);
}

// round 13
// speedup vs baseline: 3.4740x; 3.4740x over previous
#include <cuda_runtime.h>
#include <cuda_fp16.h>
#include <stdint.h>
#include <math.h>

#define NWIN     2048
#define NTOK     66
#define CDIM     256
#define NHEAD    8
#define NTHREADS 256

// fp16 weight copies, prepared at the start of every launch (graph-safe, deterministic)
__device__ __align__(16) __half g_Wq[768 * 256];
__device__ __align__(16) __half g_Wp[256 * 256];

__global__ void prep_kernel(const float* __restrict__ qkv_w,
                            const float* __restrict__ proj_w) {
    int i = blockIdx.x * blockDim.x + threadIdx.x;
    if (i < 768 * 256) g_Wq[i] = __float2half_rn(qkv_w[i]);
    if (i < 256 * 256) g_Wp[i] = __float2half_rn(proj_w[i]);
}

// ---- shared memory layout (byte offsets) ----
// Xs [80][264] h : input tokens (fp16), rows 66-79 zeroed
// Os [80][264] h : attention output accumulator (per-head slices)
// Wh [96][264] h : staged weight chunk (GEMM1 per head / proj chunks)
// Qs [80][40]  h : Q (pre-scaled)
// Ks [72][40]  h : K
// Vt [32][88]  h : V transposed  Vt[d][token]
// Pf [80][88]  h : softmax probabilities (A operand of PV)
// Sf [80][84]  f : attention logits fp32
// Tb [1800]    f : rel-pos bias table
// Bq [768]     f ; Bp [256] f
#define XS_B   0
#define OS_B   42240
#define WH_B   84480
#define QS_B   135168
#define KS_B   141568
#define VT_B   147328
#define PF_B   152960
#define SF_B   167040
#define TB_B   193920
#define BQ_B   201120
#define BP_B   204192
#define SMEM_BYTES 205216

__device__ __forceinline__ uint32_t sptr(const void* p) {
    return (uint32_t)__cvta_generic_to_shared(p);
}

#define LDSM4(r0, r1, r2, r3, p)                                              \
    asm volatile("ldmatrix.sync.aligned.m8n8.x4.shared.b16 {%0,%1,%2,%3}, [%4];" \
                 : "=r"(r0), "=r"(r1), "=r"(r2), "=r"(r3) : "r"(sptr(p)))

#define LDSM2(r0, r1, p)                                                      \
    asm volatile("ldmatrix.sync.aligned.m8n8.x2.shared.b16 {%0,%1}, [%2];"    \
                 : "=r"(r0), "=r"(r1) : "r"(sptr(p)))

#define MMA16816(d, a0, a1, a2, a3, b0, b1)                                   \
    asm volatile("mma.sync.aligned.m16n8k16.row.col.f32.f16.f16.f32 "         \
                 "{%0,%1,%2,%3}, {%4,%5,%6,%7}, {%8,%9}, {%0,%1,%2,%3};"      \
                 : "+f"((d)[0]), "+f"((d)[1]), "+f"((d)[2]), "+f"((d)[3])     \
                 : "r"(a0), "r"(a1), "r"(a2), "r"(a3), "r"(b0), "r"(b1))

__global__ void __launch_bounds__(NTHREADS, 1)
win_attn_mma(const float* __restrict__ x,
             const float* __restrict__ qkv_b,
             const float* __restrict__ tab,
             const float* __restrict__ proj_b,
             float* __restrict__ out)
{
    extern __shared__ char smraw[];
    __half* Xs = (__half*)(smraw + XS_B);
    __half* Os = (__half*)(smraw + OS_B);
    __half* Wh = (__half*)(smraw + WH_B);
    __half* Qs = (__half*)(smraw + QS_B);
    __half* Ks = (__half*)(smraw + KS_B);
    __half* Vt = (__half*)(smraw + VT_B);
    __half* Pf = (__half*)(smraw + PF_B);
    float*  Sf = (float*)(smraw + SF_B);
    float*  Tb = (float*)(smraw + TB_B);
    float*  Bq = (float*)(smraw + BQ_B);
    float*  Bp = (float*)(smraw + BP_B);

    const int tid  = threadIdx.x;
    const int warp = tid >> 5;
    const int lane = tid & 31;
    const int win  = blockIdx.x;
    const float scale = 0.17677669529663687f;  // 1/sqrt(32)

    // ---------------- stage inputs ----------------
    const float2* xg = (const float2*)(x + (size_t)win * NTOK * CDIM);
    for (int i = tid; i < NTOK * 128; i += NTHREADS) {
        int r = i >> 7, c2 = i & 127;
        float2 v = xg[i];
        *(__half2*)(Xs + r * 264 + 2 * c2) = __floats2half2_rn(v.x, v.y);
    }
    // zero padding rows 66..79 (full 264-half rows)
    for (int i = tid; i < 14 * 132; i += NTHREADS) {
        int r = 66 + i / 132, c2 = i % 132;
        *((uint32_t*)(Xs + r * 264) + c2) = 0u;
    }
    for (int i = tid; i < 1800; i += NTHREADS) Tb[i] = tab[i];
    for (int i = tid; i < 768; i += NTHREADS)  Bq[i] = qkv_b[i];
    if (tid < 256) Bp[tid] = proj_b[tid];

    // ======================= per-head loop =======================
    for (int h = 0; h < NHEAD; h++) {
        __syncthreads();   // X staged (h=0) / prev head done with Wh,Qs,Ks,Vt,Pf

        // ---- stage W_h [96 rows][256 k] fp16 into Wh (pitch 264) ----
#pragma unroll
        for (int t = 0; t < 12; t++) {
            int i  = tid + t * NTHREADS;       // 3072 uint4
            int o  = i >> 5;
            int kk = (i & 31) * 8;
            int src = ((o >> 5) * 256 + h * 32 + (o & 31)) * 256 + kk;
            *(uint4*)(Wh + o * 264 + kk) = *(const uint4*)(g_Wq + src);
        }
        __syncthreads();

        // ---- GEMM1: [80,256] @ Wh^T -> Q/K/V  (5 m-tiles x 6 n16-tiles) ----
        for (int job = warp; job < 30; job += 8) {
            int mt = job / 6, nt = job % 6;
            float dacc[2][4] = {{0.f, 0.f, 0.f, 0.f}, {0.f, 0.f, 0.f, 0.f}};
            const __half* Abase = Xs + (mt * 16 + (lane & 15)) * 264 + ((lane >> 4) * 8);
            const __half* Bbase = Wh + (nt * 16 + (lane & 15)) * 264 + ((lane >> 4) * 8);
#pragma unroll
            for (int ks = 0; ks < 16; ks++) {
                uint32_t a0, a1, a2, a3, b0, b1, b2, b3;
                LDSM4(a0, a1, a2, a3, Abase + ks * 16);
                LDSM4(b0, b1, b2, b3, Bbase + ks * 16);
                MMA16816(dacc[0], a0, a1, a2, a3, b0, b2);
                MMA16816(dacc[1], a0, a1, a2, a3, b1, b3);
            }
            int r0i = mt * 16 + (lane >> 2);
#pragma unroll
            for (int st = 0; st < 2; st++) {
                int cb = nt * 16 + st * 8 + (lane & 3) * 2;
                int s  = cb >> 5, dd = cb & 31;
                float b0v = Bq[s * 256 + h * 32 + dd];
                float b1v = Bq[s * 256 + h * 32 + dd + 1];
#pragma unroll
                for (int part = 0; part < 2; part++) {
                    int r = r0i + part * 8;
                    float v0 = dacc[st][part * 2 + 0] + b0v;
                    float v1 = dacc[st][part * 2 + 1] + b1v;
                    if (s == 0) {
                        *(__half2*)(Qs + r * 40 + dd) =
                            __floats2half2_rn(v0 * scale, v1 * scale);
                    } else if (s == 1) {
                        if (r < 72)
                            *(__half2*)(Ks + r * 40 + dd) = __floats2half2_rn(v0, v1);
                    } else {
                        Vt[dd * 88 + r]       = __float2half_rn(v0);
                        Vt[(dd + 1) * 88 + r] = __float2half_rn(v1);
                    }
                }
            }
        }
        __syncthreads();

        // ---- QK^T: S[80,72] = Q @ K^T  (5 m x 9 n8), bias added in fp32 ----
        for (int job = warp; job < 45; job += 8) {
            int mt = job / 9, nt = job % 9;
            float dacc[4] = {0.f, 0.f, 0.f, 0.f};
            const __half* Abase = Qs + (mt * 16 + (lane & 15)) * 40 + ((lane >> 4) * 8);
            const __half* Bbase = Ks + (nt * 8 + (lane & 7)) * 40 + (((lane >> 3) & 1) * 8);
#pragma unroll
            for (int ks = 0; ks < 2; ks++) {
                uint32_t a0, a1, a2, a3, b0, b1;
                LDSM4(a0, a1, a2, a3, Abase + ks * 16);
                LDSM2(b0, b1, Bbase + ks * 16);
                MMA16816(dacc, a0, a1, a2, a3, b0, b1);
            }
            int R = mt * 16 + (lane >> 2);
            int C = nt * 8 + (lane & 3) * 2;
#pragma unroll
            for (int part = 0; part < 2; part++) {
                int r = R + part * 8;
                if (r < 66) {
#pragma unroll
                    for (int e = 0; e < 2; e++) {
                        int c = C + e;
                        float v = dacc[part * 2 + e];
                        if (r >= 2 && c >= 2 && c < 66) {
                            int p = r - 2, q = c - 2;
                            int dy = (p >> 3) - (q >> 3) + 7;
                            int dx = (p & 7) - (q & 7) + 7;
                            v += Tb[(dy * 15 + dx) * 8 + h];
                        }
                        Sf[r * 84 + c] = v;
                    }
                }
            }
        }
        __syncthreads();

        // ---- softmax (warp per row), write P fp16 with zeroed pad cols ----
        for (int r = warp; r < NTOK; r += 8) {
            const float* srow = Sf + r * 84;
            float v0 = srow[lane];
            float v1 = srow[32 + lane];
            float v2 = (lane < 2) ? srow[64 + lane] : -INFINITY;
            float m = fmaxf(v0, fmaxf(v1, v2));
#pragma unroll
            for (int off = 16; off > 0; off >>= 1)
                m = fmaxf(m, __shfl_xor_sync(0xffffffffu, m, off));
            float e0 = __expf(v0 - m);
            float e1 = __expf(v1 - m);
            float e2 = (lane < 2) ? __expf(v2 - m) : 0.f;
            float s = e0 + e1 + e2;
#pragma unroll
            for (int off = 16; off > 0; off >>= 1)
                s += __shfl_xor_sync(0xffffffffu, s, off);
            float inv = __frcp_rn(s);
            __half* prow = Pf + r * 88;
            prow[lane]      = __float2half_rn(e0 * inv);
            prow[32 + lane] = __float2half_rn(e1 * inv);
            if (lane < 16)
                prow[64 + lane] = __float2half_rn((lane < 2) ? e2 * inv : 0.f);
        }
        __syncthreads();

        // ---- PV: O_h[80,32] = P[80,80] @ V  (5 m x 2 n16) ----
        for (int job = warp; job < 10; job += 8) {
            int mt = job >> 1, nt = job & 1;
            float dacc[2][4] = {{0.f, 0.f, 0.f, 0.f}, {0.f, 0.f, 0.f, 0.f}};
            const __half* Abase = Pf + (mt * 16 + (lane & 15)) * 88 + ((lane >> 4) * 8);
            const __half* Bbase = Vt + (nt * 16 + (lane & 15)) * 88 + ((lane >> 4) * 8);
#pragma unroll
            for (int ks = 0; ks < 5; ks++) {
                uint32_t a0, a1, a2, a3, b0, b1, b2, b3;
                LDSM4(a0, a1, a2, a3, Abase + ks * 16);
                LDSM4(b0, b1, b2, b3, Bbase + ks * 16);
                MMA16816(dacc[0], a0, a1, a2, a3, b0, b2);
                MMA16816(dacc[1], a0, a1, a2, a3, b1, b3);
            }
            int r0i = mt * 16 + (lane >> 2);
#pragma unroll
            for (int st = 0; st < 2; st++) {
                int c = h * 32 + nt * 16 + st * 8 + (lane & 3) * 2;
#pragma unroll
                for (int part = 0; part < 2; part++) {
                    int r = r0i + part * 8;
                    *(__half2*)(Os + r * 264 + c) =
                        __floats2half2_rn(dacc[st][part * 2 + 0],
                                          dacc[st][part * 2 + 1]);
                }
            }
        }
    }
    __syncthreads();

    // ======================= output projection =======================
    for (int chunk = 0; chunk < 3; chunk++) {
        int o0   = chunk * 96;
        int rows = (chunk == 2) ? 64 : 96;
        // stage proj weight chunk
        int tot4 = rows * 32;
        for (int i = tid; i < tot4; i += NTHREADS) {
            int o = i >> 5, kk = (i & 31) * 8;
            *(uint4*)(Wh + o * 264 + kk) = *(const uint4*)(g_Wp + (o0 + o) * 256 + kk);
        }
        __syncthreads();

        int ntiles = rows / 16;                 // 6, 6, 4
        for (int job = warp; job < 5 * ntiles; job += 8) {
            int mt = job / ntiles, nt = job % ntiles;
            float dacc[2][4] = {{0.f, 0.f, 0.f, 0.f}, {0.f, 0.f, 0.f, 0.f}};
            const __half* Abase = Os + (mt * 16 + (lane & 15)) * 264 + ((lane >> 4) * 8);
            const __half* Bbase = Wh + (nt * 16 + (lane & 15)) * 264 + ((lane >> 4) * 8);
#pragma unroll
            for (int ks = 0; ks < 16; ks++) {
                uint32_t a0, a1, a2, a3, b0, b1, b2, b3;
                LDSM4(a0, a1, a2, a3, Abase + ks * 16);
                LDSM4(b0, b1, b2, b3, Bbase + ks * 16);
                MMA16816(dacc[0], a0, a1, a2, a3, b0, b2);
                MMA16816(dacc[1], a0, a1, a2, a3, b1, b3);
            }
            int r0i = mt * 16 + (lane >> 2);
#pragma unroll
            for (int st = 0; st < 2; st++) {
                int c = o0 + nt * 16 + st * 8 + (lane & 3) * 2;
                float b0v = Bp[c], b1v = Bp[c + 1];
#pragma unroll
                for (int part = 0; part < 2; part++) {
                    int r = r0i + part * 8;
                    if (r < NTOK) {
                        float2 v;
                        v.x = dacc[st][part * 2 + 0] + b0v;
                        v.y = dacc[st][part * 2 + 1] + b1v;
                        *(float2*)(out + ((size_t)win * NTOK + r) * CDIM + c) = v;
                    }
                }
            }
        }
        __syncthreads();
    }
}

extern "C" void kernel_launch(void* const* d_in, const int* in_sizes, int n_in,
                              void* d_out, int out_size) {
    (void)in_sizes; (void)n_in; (void)out_size;
    const float* x      = (const float*)d_in[0];
    const float* qkv_w  = (const float*)d_in[1];
    const float* qkv_b  = (const float*)d_in[2];
    const float* tab    = (const float*)d_in[3];
    const float* proj_w = (const float*)d_in[4];
    const float* proj_b = (const float*)d_in[5];
    float* out = (float*)d_out;

    prep_kernel<<<768, 256>>>(qkv_w, proj_w);

    cudaFuncSetAttribute(win_attn_mma,
                         cudaFuncAttributeMaxDynamicSharedMemorySize, SMEM_BYTES);
    win_attn_mma<<<NWIN, NTHREADS, SMEM_BYTES>>>(
        x, qkv_b, tab, proj_b, out);
}

// round 14
// speedup vs baseline: 4.0343x; 1.1613x over previous
#include <cuda_runtime.h>
#include <cuda_fp16.h>
#include <stdint.h>
#include <math.h>

#define NWIN     2048
#define NTOK     66
#define CDIM     256
#define NHEAD    8
#define NTHREADS 256

// fp16 weight copies, prepared at the start of every launch (graph-safe, deterministic)
__device__ __align__(16) __half g_Wq[768 * 256];
__device__ __align__(16) __half g_Wp[256 * 256];

__global__ void prep_kernel(const float* __restrict__ qkv_w,
                            const float* __restrict__ proj_w) {
    int i = blockIdx.x * blockDim.x + threadIdx.x;
    if (i < 768 * 256) g_Wq[i] = __float2half_rn(qkv_w[i]);
    if (i < 256 * 256) g_Wp[i] = __float2half_rn(proj_w[i]);
}

// ---- shared memory layout (byte offsets) ----
// Xs [80][264] h ; Os [80][264] h ; Wh 2x[96][264] h (double buffer)
// Qs [80][40] h ; Ks [72][40] h ; Vt [32][88] h
// Tb [1800] f ; IdxT [64*64] u16 ; Bq [768] f ; Bp [256] f
#define XS_B   0
#define OS_B   42240
#define WH_B   84480
#define WH_HALVES 25344          // 96*264
#define QS_B   185856
#define KS_B   192256
#define VT_B   198016
#define TB_B   203648
#define IX_B   210848
#define BQ_B   219040
#define BP_B   222112
#define SMEM_BYTES 223136

__device__ __forceinline__ uint32_t sptr(const void* p) {
    return (uint32_t)__cvta_generic_to_shared(p);
}

#define LDSM4(r0, r1, r2, r3, p)                                              \
    asm volatile("ldmatrix.sync.aligned.m8n8.x4.shared.b16 {%0,%1,%2,%3}, [%4];" \
                 : "=r"(r0), "=r"(r1), "=r"(r2), "=r"(r3) : "r"(sptr(p)))

#define LDSM2(r0, r1, p)                                                      \
    asm volatile("ldmatrix.sync.aligned.m8n8.x2.shared.b16 {%0,%1}, [%2];"    \
                 : "=r"(r0), "=r"(r1) : "r"(sptr(p)))

#define MMA16816(d, a0, a1, a2, a3, b0, b1)                                   \
    asm volatile("mma.sync.aligned.m16n8k16.row.col.f32.f16.f16.f32 "         \
                 "{%0,%1,%2,%3}, {%4,%5,%6,%7}, {%8,%9}, {%0,%1,%2,%3};"      \
                 : "+f"((d)[0]), "+f"((d)[1]), "+f"((d)[2]), "+f"((d)[3])     \
                 : "r"(a0), "r"(a1), "r"(a2), "r"(a3), "r"(b0), "r"(b1))

__device__ __forceinline__ uint32_t pk2(float x, float y) {
    __half2 h = __floats2half2_rn(x, y);
    return *(uint32_t*)&h;
}

// stage weight chunk: 0..7 = qkv head chunks [96][256], 8..10 = proj chunks
__device__ __forceinline__ void stage_chunk(int chunk, __half* Wbuf,
                                            int t0, int nthr) {
    if (chunk < 8) {
        for (int i = t0; i < 3072; i += nthr) {
            int o = i >> 5, kk = (i & 31) * 8;
            int src = ((o >> 5) * 256 + chunk * 32 + (o & 31)) * 256 + kk;
            *(uint4*)(Wbuf + o * 264 + kk) = *(const uint4*)(g_Wq + src);
        }
    } else {
        int o0  = (chunk - 8) * 96;
        int tot = ((chunk == 10) ? 64 : 96) * 32;
        for (int i = t0; i < tot; i += nthr) {
            int o = i >> 5, kk = (i & 31) * 8;
            *(uint4*)(Wbuf + o * 264 + kk) = *(const uint4*)(g_Wp + (o0 + o) * 256 + kk);
        }
    }
}

__global__ void __launch_bounds__(NTHREADS, 1)
win_attn_mma(const float* __restrict__ x,
             const float* __restrict__ qkv_b,
             const float* __restrict__ tab,
             const float* __restrict__ proj_b,
             float* __restrict__ out)
{
    extern __shared__ char smraw[];
    __half* Xs = (__half*)(smraw + XS_B);
    __half* Os = (__half*)(smraw + OS_B);
    __half* Wh = (__half*)(smraw + WH_B);
    __half* Qs = (__half*)(smraw + QS_B);
    __half* Ks = (__half*)(smraw + KS_B);
    __half* Vt = (__half*)(smraw + VT_B);
    float*  Tb = (float*)(smraw + TB_B);
    uint16_t* IdxT = (uint16_t*)(smraw + IX_B);
    float*  Bq = (float*)(smraw + BQ_B);
    float*  Bp = (float*)(smraw + BP_B);

    const int tid  = threadIdx.x;
    const int warp = tid >> 5;
    const int lane = tid & 31;
    const int win  = blockIdx.x;
    const float scale = 0.17677669529663687f;  // 1/sqrt(32)

    // ---------------- stage inputs + first weight chunk ----------------
    const float2* xg = (const float2*)(x + (size_t)win * NTOK * CDIM);
    for (int i = tid; i < NTOK * 128; i += NTHREADS) {
        int r = i >> 7, c2 = i & 127;
        float2 v = xg[i];
        *(__half2*)(Xs + r * 264 + 2 * c2) = __floats2half2_rn(v.x, v.y);
    }
    for (int i = tid; i < 14 * 132; i += NTHREADS) {   // zero pad rows 66..79
        int r = 66 + i / 132, c2 = i % 132;
        *((uint32_t*)(Xs + r * 264) + c2) = 0u;
    }
    for (int i = tid; i < 1800; i += NTHREADS) Tb[i] = tab[i];
    for (int i = tid; i < 4096; i += NTHREADS) {
        int p = i >> 6, q = i & 63;
        int dy = (p >> 3) - (q >> 3) + 7;
        int dx = (p & 7) - (q & 7) + 7;
        IdxT[i] = (uint16_t)((dy * 15 + dx) * 8);
    }
    for (int i = tid; i < 768; i += NTHREADS)  Bq[i] = qkv_b[i];
    if (tid < 256) Bp[tid] = proj_b[tid];
    stage_chunk(0, Wh, tid, NTHREADS);
    __syncthreads();

    // ======================= per-head loop =======================
    for (int h = 0; h < NHEAD; h++) {
        const __half* Wc = Wh + (h & 1) * WH_HALVES;

        // ---- GEMM1: [80,256] @ Wc^T -> Q/K/V  (all 8 warps, 30 jobs) ----
        for (int job = warp; job < 30; job += 8) {
            int mt = job / 6, nt = job % 6;
            float dacc[2][4] = {{0.f, 0.f, 0.f, 0.f}, {0.f, 0.f, 0.f, 0.f}};
            const __half* Abase = Xs + (mt * 16 + (lane & 15)) * 264 + ((lane >> 4) * 8);
            const __half* Bbase = Wc + (nt * 16 + (lane & 15)) * 264 + ((lane >> 4) * 8);
#pragma unroll
            for (int ks = 0; ks < 16; ks++) {
                uint32_t a0, a1, a2, a3, b0, b1, b2, b3;
                LDSM4(a0, a1, a2, a3, Abase + ks * 16);
                LDSM4(b0, b1, b2, b3, Bbase + ks * 16);
                MMA16816(dacc[0], a0, a1, a2, a3, b0, b2);
                MMA16816(dacc[1], a0, a1, a2, a3, b1, b3);
            }
            int r0i = mt * 16 + (lane >> 2);
#pragma unroll
            for (int st = 0; st < 2; st++) {
                int cb = nt * 16 + st * 8 + (lane & 3) * 2;
                int s  = cb >> 5, dd = cb & 31;
                float b0v = Bq[s * 256 + h * 32 + dd];
                float b1v = Bq[s * 256 + h * 32 + dd + 1];
#pragma unroll
                for (int part = 0; part < 2; part++) {
                    int r = r0i + part * 8;
                    float v0 = dacc[st][part * 2 + 0] + b0v;
                    float v1 = dacc[st][part * 2 + 1] + b1v;
                    if (s == 0) {
                        *(__half2*)(Qs + r * 40 + dd) =
                            __floats2half2_rn(v0 * scale, v1 * scale);
                    } else if (s == 1) {
                        if (r < 72)
                            *(__half2*)(Ks + r * 40 + dd) = __floats2half2_rn(v0, v1);
                    } else {
                        Vt[dd * 88 + r]       = __float2half_rn(v0);
                        Vt[(dd + 1) * 88 + r] = __float2half_rn(v1);
                    }
                }
            }
        }
        __syncthreads();

        if (warp < 5) {
            // ======= attention for m-tile `warp`: QK^T -> softmax -> PV, all in regs =======
            const int mt = warp;
            const int r0 = mt * 16 + (lane >> 2);
            const int r1 = r0 + 8;
            const int cbase = (lane & 3) * 2;

            // Q A-fragments (k=32: two k16 steps)
            const __half* Aq = Qs + (mt * 16 + (lane & 15)) * 40 + ((lane >> 4) * 8);
            uint32_t qa[2][4];
            LDSM4(qa[0][0], qa[0][1], qa[0][2], qa[0][3], Aq);
            LDSM4(qa[1][0], qa[1][1], qa[1][2], qa[1][3], Aq + 16);

            // S tiles [9][4]
            float S[9][4];
#pragma unroll
            for (int nt = 0; nt < 9; nt++) {
                S[nt][0] = S[nt][1] = S[nt][2] = S[nt][3] = 0.f;
                const __half* Bk = Ks + (nt * 8 + (lane & 7)) * 40 + (((lane >> 3) & 1) * 8);
                uint32_t b0, b1;
                LDSM2(b0, b1, Bk);
                MMA16816(S[nt], qa[0][0], qa[0][1], qa[0][2], qa[0][3], b0, b1);
                LDSM2(b0, b1, Bk + 16);
                MMA16816(S[nt], qa[1][0], qa[1][1], qa[1][2], qa[1][3], b0, b1);
            }

            // bias + pad-col mask
#pragma unroll
            for (int nt = 0; nt < 9; nt++) {
#pragma unroll
                for (int e = 0; e < 2; e++) {
                    int c = nt * 8 + cbase + e;
                    if (c >= 66) {
                        S[nt][e] = -1e30f; S[nt][2 + e] = -1e30f;
                    } else if (c >= 2) {
                        int q = c - 2;
                        if (r0 >= 2 && r0 < 66)
                            S[nt][e]     += Tb[IdxT[(r0 - 2) * 64 + q] + h];
                        if (r1 < 66)
                            S[nt][2 + e] += Tb[IdxT[(r1 - 2) * 64 + q] + h];
                    }
                }
            }

            // softmax across the row (quad reduction: lanes differ only in lane&3)
            float m0 = -1e30f, m1 = -1e30f;
#pragma unroll
            for (int nt = 0; nt < 9; nt++) {
                m0 = fmaxf(m0, fmaxf(S[nt][0], S[nt][1]));
                m1 = fmaxf(m1, fmaxf(S[nt][2], S[nt][3]));
            }
            m0 = fmaxf(m0, __shfl_xor_sync(0xffffffffu, m0, 1));
            m0 = fmaxf(m0, __shfl_xor_sync(0xffffffffu, m0, 2));
            m1 = fmaxf(m1, __shfl_xor_sync(0xffffffffu, m1, 1));
            m1 = fmaxf(m1, __shfl_xor_sync(0xffffffffu, m1, 2));
            float s0 = 0.f, s1 = 0.f;
#pragma unroll
            for (int nt = 0; nt < 9; nt++) {
                S[nt][0] = __expf(S[nt][0] - m0); s0 += S[nt][0];
                S[nt][1] = __expf(S[nt][1] - m0); s0 += S[nt][1];
                S[nt][2] = __expf(S[nt][2] - m1); s1 += S[nt][2];
                S[nt][3] = __expf(S[nt][3] - m1); s1 += S[nt][3];
            }
            s0 += __shfl_xor_sync(0xffffffffu, s0, 1);
            s0 += __shfl_xor_sync(0xffffffffu, s0, 2);
            s1 += __shfl_xor_sync(0xffffffffu, s1, 1);
            s1 += __shfl_xor_sync(0xffffffffu, s1, 2);
            float inv0 = __frcp_rn(s0), inv1 = __frcp_rn(s1);

            // repack S(C-frag) -> P(A-frag): c-layout == a-layout, zero shuffles
            uint32_t pa[5][4];
#pragma unroll
            for (int kt = 0; kt < 5; kt++) {
                int t0 = 2 * kt, t1 = 2 * kt + 1;
                pa[kt][0] = pk2(S[t0][0] * inv0, S[t0][1] * inv0);
                pa[kt][1] = pk2(S[t0][2] * inv1, S[t0][3] * inv1);
                if (t1 < 9) {
                    pa[kt][2] = pk2(S[t1][0] * inv0, S[t1][1] * inv0);
                    pa[kt][3] = pk2(S[t1][2] * inv1, S[t1][3] * inv1);
                } else {
                    pa[kt][2] = 0u; pa[kt][3] = 0u;   // k cols 72..79
                }
            }

            // PV: O[16][32] += P[16][80] @ V[80][32]
            float dO[4][4];
#pragma unroll
            for (int i = 0; i < 4; i++)
                dO[i][0] = dO[i][1] = dO[i][2] = dO[i][3] = 0.f;
            const __half* Bv = Vt + (lane & 15) * 88 + ((lane >> 4) * 8);
#pragma unroll
            for (int kt = 0; kt < 5; kt++) {
                uint32_t b0, b1, b2, b3;
                LDSM4(b0, b1, b2, b3, Bv + kt * 16);            // dims 0..15
                MMA16816(dO[0], pa[kt][0], pa[kt][1], pa[kt][2], pa[kt][3], b0, b2);
                MMA16816(dO[1], pa[kt][0], pa[kt][1], pa[kt][2], pa[kt][3], b1, b3);
                LDSM4(b0, b1, b2, b3, Bv + 16 * 88 + kt * 16);  // dims 16..31
                MMA16816(dO[2], pa[kt][0], pa[kt][1], pa[kt][2], pa[kt][3], b0, b2);
                MMA16816(dO[3], pa[kt][0], pa[kt][1], pa[kt][2], pa[kt][3], b1, b3);
            }
#pragma unroll
            for (int nt8 = 0; nt8 < 4; nt8++) {
                int c = h * 32 + nt8 * 8 + cbase;
                *(__half2*)(Os + r0 * 264 + c) = __floats2half2_rn(dO[nt8][0], dO[nt8][1]);
                *(__half2*)(Os + r1 * 264 + c) = __floats2half2_rn(dO[nt8][2], dO[nt8][3]);
            }
        } else {
            // warps 5-7: prefetch next weight chunk into the other buffer
            stage_chunk(h + 1, Wh + ((h + 1) & 1) * WH_HALVES, tid - 160, 96);
        }
        __syncthreads();
    }

    // ======================= output projection =======================
    // chunk 8 (proj c0) was staged into buf 0 during head-7 attention
    for (int c = 0; c < 3; c++) {
        const __half* Wc = Wh + (c & 1) * WH_HALVES;   // 8->0, 9->1, 10->0
        int ntiles = (c == 2) ? 4 : 6;
        int o0 = c * 96;
        bool compute = (c == 2) || (warp < 5);
        int jb   = (c == 2) ? warp : warp;
        int jstep = (c == 2) ? 8 : 5;
        if (compute) {
            for (int job = jb; job < 5 * ntiles; job += jstep) {
                int mt = job / ntiles, nt = job % ntiles;
                float dacc[2][4] = {{0.f, 0.f, 0.f, 0.f}, {0.f, 0.f, 0.f, 0.f}};
                const __half* Abase = Os + (mt * 16 + (lane & 15)) * 264 + ((lane >> 4) * 8);
                const __half* Bbase = Wc + (nt * 16 + (lane & 15)) * 264 + ((lane >> 4) * 8);
#pragma unroll
                for (int ks = 0; ks < 16; ks++) {
                    uint32_t a0, a1, a2, a3, b0, b1, b2, b3;
                    LDSM4(a0, a1, a2, a3, Abase + ks * 16);
                    LDSM4(b0, b1, b2, b3, Bbase + ks * 16);
                    MMA16816(dacc[0], a0, a1, a2, a3, b0, b2);
                    MMA16816(dacc[1], a0, a1, a2, a3, b1, b3);
                }
                int r0i = mt * 16 + (lane >> 2);
#pragma unroll
                for (int st = 0; st < 2; st++) {
                    int cc = o0 + nt * 16 + st * 8 + (lane & 3) * 2;
                    float b0v = Bp[cc], b1v = Bp[cc + 1];
#pragma unroll
                    for (int part = 0; part < 2; part++) {
                        int r = r0i + part * 8;
                        if (r < NTOK) {
                            float2 v;
                            v.x = dacc[st][part * 2 + 0] + b0v;
                            v.y = dacc[st][part * 2 + 1] + b1v;
                            *(float2*)(out + ((size_t)win * NTOK + r) * CDIM + cc) = v;
                        }
                    }
                }
            }
        } else {
            // warps 5-7: stage next proj chunk (9 -> buf1, 10 -> buf0)
            stage_chunk(9 + c, Wh + ((9 + c) & 1) * WH_HALVES, tid - 160, 96);
        }
        if (c < 2) __syncthreads();
    }
}

extern "C" void kernel_launch(void* const* d_in, const int* in_sizes, int n_in,
                              void* d_out, int out_size) {
    (void)in_sizes; (void)n_in; (void)out_size;
    const float* x      = (const float*)d_in[0];
    const float* qkv_w  = (const float*)d_in[1];
    const float* qkv_b  = (const float*)d_in[2];
    const float* tab    = (const float*)d_in[3];
    const float* proj_w = (const float*)d_in[4];
    const float* proj_b = (const float*)d_in[5];
    float* out = (float*)d_out;

    prep_kernel<<<768, 256>>>(qkv_w, proj_w);

    cudaFuncSetAttribute(win_attn_mma,
                         cudaFuncAttributeMaxDynamicSharedMemorySize, SMEM_BYTES);
    win_attn_mma<<<NWIN, NTHREADS, SMEM_BYTES>>>(
        x, qkv_b, tab, proj_b, out);
}

// round 15
// speedup vs baseline: 5.9653x; 1.4786x over previous
#include <cuda_runtime.h>
#include <cuda_fp16.h>
#include <stdint.h>
#include <math.h>

#define NWIN     2048
#define NTOK     66
#define CDIM     256
#define NHEAD    8
#define NTHREADS 512

// fp16 weight copies, prepared at the start of every launch (graph-safe, deterministic)
__device__ __align__(16) __half g_Wq[768 * 256];
__device__ __align__(16) __half g_Wp[256 * 256];

__global__ void prep_kernel(const float* __restrict__ qkv_w,
                            const float* __restrict__ proj_w) {
    int i = blockIdx.x * blockDim.x + threadIdx.x;
    if (i < 768 * 256) g_Wq[i] = __float2half_rn(qkv_w[i]);
    if (i < 256 * 256) g_Wp[i] = __float2half_rn(proj_w[i]);
}

// ---- shared memory layout (byte offsets) ----
// Xs [80][264] h ; Os [80][264] h ; Wh [192][264] h (2-head / proj chunk)
// Qs [2][80][40] h ; Ks [2][72][40] h ; Vt [2][32][88] h
// Tb fp16[1800] ; IdxT u8[4096] ; Bq fp16[768] ; Bp f32[256]
#define XS_B   0
#define OS_B   42240
#define WH_B   84480
#define QS_B   185856
#define KS_B   198656
#define VT_B   210176
#define TB_B   221440
#define IX_B   225040
#define BQ_B   229136
#define BP_B   230672
#define SMEM_BYTES 231696

__device__ __forceinline__ uint32_t sptr(const void* p) {
    return (uint32_t)__cvta_generic_to_shared(p);
}

#define LDSM4(r0, r1, r2, r3, p)                                              \
    asm volatile("ldmatrix.sync.aligned.m8n8.x4.shared.b16 {%0,%1,%2,%3}, [%4];" \
                 : "=r"(r0), "=r"(r1), "=r"(r2), "=r"(r3) : "r"(sptr(p)))

#define LDSM2(r0, r1, p)                                                      \
    asm volatile("ldmatrix.sync.aligned.m8n8.x2.shared.b16 {%0,%1}, [%2];"    \
                 : "=r"(r0), "=r"(r1) : "r"(sptr(p)))

#define MMA16816(d, a0, a1, a2, a3, b0, b1)                                   \
    asm volatile("mma.sync.aligned.m16n8k16.row.col.f32.f16.f16.f32 "         \
                 "{%0,%1,%2,%3}, {%4,%5,%6,%7}, {%8,%9}, {%0,%1,%2,%3};"      \
                 : "+f"((d)[0]), "+f"((d)[1]), "+f"((d)[2]), "+f"((d)[3])     \
                 : "r"(a0), "r"(a1), "r"(a2), "r"(a3), "r"(b0), "r"(b1))

__device__ __forceinline__ uint32_t pk2(float x, float y) {
    __half2 h = __floats2half2_rn(x, y);
    return *(uint32_t*)&h;
}

// stage 2 heads' qkv weights (pair p -> heads 2p, 2p+1) into Wh[192][264]
__device__ __forceinline__ void stage_qkv_pair(int pair, __half* Wh,
                                               int t0, int nthr) {
    for (int i = t0; i < 6144; i += nthr) {
        int o = i >> 5, kk = (i & 31) * 8;
        int hh = o / 96, ol = o % 96;
        int s = ol >> 5, jj = ol & 31;
        int head = pair * 2 + hh;
        *(uint4*)(Wh + o * 264 + kk) =
            *(const uint4*)(g_Wq + ((s * 256 + head * 32 + jj) * 256 + kk));
    }
}

// stage proj rows [row0, row0+nrows) into dst (pitch 264)
__device__ __forceinline__ void stage_wp(int row0, int nrows, __half* dst,
                                         int t0, int nthr) {
    for (int i = t0; i < nrows * 32; i += nthr) {
        int o = i >> 5, kk = (i & 31) * 8;
        *(uint4*)(dst + o * 264 + kk) = *(const uint4*)(g_Wp + (row0 + o) * 256 + kk);
    }
}

__global__ void __launch_bounds__(NTHREADS, 1)
win_attn_mma(const float* __restrict__ x,
             const float* __restrict__ qkv_b,
             const float* __restrict__ tab,
             const float* __restrict__ proj_b,
             float* __restrict__ out)
{
    extern __shared__ char smraw[];
    __half* Xs = (__half*)(smraw + XS_B);
    __half* Os = (__half*)(smraw + OS_B);
    __half* Wh = (__half*)(smraw + WH_B);
    __half* Qs = (__half*)(smraw + QS_B);
    __half* Ks = (__half*)(smraw + KS_B);
    __half* Vt = (__half*)(smraw + VT_B);
    __half* Tb = (__half*)(smraw + TB_B);
    unsigned char* IdxT = (unsigned char*)(smraw + IX_B);
    __half* Bq = (__half*)(smraw + BQ_B);
    float*  Bp = (float*)(smraw + BP_B);
    __half* PB = (__half*)(smraw + QS_B);   // proj chunk1 reuses dead QKV region

    const int tid  = threadIdx.x;
    const int warp = tid >> 5;
    const int lane = tid & 31;
    const int win  = blockIdx.x;
    const float scale = 0.17677669529663687f;  // 1/sqrt(32)

    // ---------------- stage inputs + first weight pair ----------------
    const float2* xg = (const float2*)(x + (size_t)win * NTOK * CDIM);
    for (int i = tid; i < NTOK * 128; i += NTHREADS) {
        int r = i >> 7, c2 = i & 127;
        float2 v = xg[i];
        *(__half2*)(Xs + r * 264 + 2 * c2) = __floats2half2_rn(v.x, v.y);
    }
    for (int i = tid; i < 14 * 132; i += NTHREADS) {   // zero pad rows 66..79
        int r = 66 + i / 132, c2 = i % 132;
        *((uint32_t*)(Xs + r * 264) + c2) = 0u;
    }
    for (int i = tid; i < 1800; i += NTHREADS) Tb[i] = __float2half_rn(tab[i]);
    for (int i = tid; i < 4096; i += NTHREADS) {
        int p = i >> 6, q = i & 63;
        int dy = (p >> 3) - (q >> 3) + 7;
        int dx = (p & 7) - (q & 7) + 7;
        IdxT[i] = (unsigned char)(dy * 15 + dx);
    }
    for (int i = tid; i < 768; i += NTHREADS) Bq[i] = __float2half_rn(qkv_b[i]);
    if (tid < 256) Bp[tid] = proj_b[tid];
    stage_qkv_pair(0, Wh, tid, NTHREADS);
    __syncthreads();

    // ================= 4 iterations of 2 heads each =================
    for (int it = 0; it < 4; it++) {
        // ---- GEMM1: 12 n16-column jobs (B-frag reused over 5 m-tiles) ----
        if (warp < 12) {
            int job = warp;
            int hh = job / 6, n16 = job % 6;
            int h = it * 2 + hh;
            float acc[5][2][4];
#pragma unroll
            for (int i = 0; i < 5; i++)
#pragma unroll
                for (int j = 0; j < 2; j++)
                    acc[i][j][0] = acc[i][j][1] = acc[i][j][2] = acc[i][j][3] = 0.f;

            const __half* Brow = Wh + (hh * 96 + n16 * 16 + (lane & 15)) * 264 + ((lane >> 4) * 8);
            const __half* Arow = Xs + (lane & 15) * 264 + ((lane >> 4) * 8);
#pragma unroll
            for (int ks = 0; ks < 16; ks++) {
                uint32_t b0, b1, b2, b3;
                LDSM4(b0, b1, b2, b3, Brow + ks * 16);
#pragma unroll
                for (int mt = 0; mt < 5; mt++) {
                    uint32_t a0, a1, a2, a3;
                    LDSM4(a0, a1, a2, a3, Arow + mt * 16 * 264 + ks * 16);
                    MMA16816(acc[mt][0], a0, a1, a2, a3, b0, b2);
                    MMA16816(acc[mt][1], a0, a1, a2, a3, b1, b3);
                }
            }
            __half* Qsh = Qs + hh * 3200;
            __half* Ksh = Ks + hh * 2880;
            __half* Vth = Vt + hh * 2816;
#pragma unroll
            for (int st = 0; st < 2; st++) {
                int cb = n16 * 16 + st * 8 + (lane & 3) * 2;
                int s = cb >> 5, dd = cb & 31;
                float b0v = __half2float(Bq[s * 256 + h * 32 + dd]);
                float b1v = __half2float(Bq[s * 256 + h * 32 + dd + 1]);
#pragma unroll
                for (int mt = 0; mt < 5; mt++) {
                    int r0 = mt * 16 + (lane >> 2);
#pragma unroll
                    for (int part = 0; part < 2; part++) {
                        int r = r0 + part * 8;
                        float v0 = acc[mt][st][part * 2 + 0] + b0v;
                        float v1 = acc[mt][st][part * 2 + 1] + b1v;
                        if (s == 0) {
                            *(__half2*)(Qsh + r * 40 + dd) =
                                __floats2half2_rn(v0 * scale, v1 * scale);
                        } else if (s == 1) {
                            if (r < 72)
                                *(__half2*)(Ksh + r * 40 + dd) = __floats2half2_rn(v0, v1);
                        } else {
                            Vth[dd * 88 + r]       = __float2half_rn(v0);
                            Vth[(dd + 1) * 88 + r] = __float2half_rn(v1);
                        }
                    }
                }
            }
        }
        __syncthreads();

        if (warp < 10) {
            // ---- attention for (m-tile, head): all in registers ----
            const int mt = warp >> 1, hh = warp & 1;
            const int h = it * 2 + hh;
            const __half* Qsh = Qs + hh * 3200;
            const __half* Ksh = Ks + hh * 2880;
            const __half* Vth = Vt + hh * 2816;
            const int r0 = mt * 16 + (lane >> 2);
            const int r1 = r0 + 8;
            const int cbase = (lane & 3) * 2;

            const __half* Aq = Qsh + (mt * 16 + (lane & 15)) * 40 + ((lane >> 4) * 8);
            uint32_t qa[2][4];
            LDSM4(qa[0][0], qa[0][1], qa[0][2], qa[0][3], Aq);
            LDSM4(qa[1][0], qa[1][1], qa[1][2], qa[1][3], Aq + 16);

            float S[9][4];
#pragma unroll
            for (int nt = 0; nt < 9; nt++) {
                S[nt][0] = S[nt][1] = S[nt][2] = S[nt][3] = 0.f;
                const __half* Bk = Ksh + (nt * 8 + (lane & 7)) * 40 + (((lane >> 3) & 1) * 8);
                uint32_t b0, b1;
                LDSM2(b0, b1, Bk);
                MMA16816(S[nt], qa[0][0], qa[0][1], qa[0][2], qa[0][3], b0, b1);
                LDSM2(b0, b1, Bk + 16);
                MMA16816(S[nt], qa[1][0], qa[1][1], qa[1][2], qa[1][3], b0, b1);
            }

#pragma unroll
            for (int nt = 0; nt < 9; nt++) {
#pragma unroll
                for (int e = 0; e < 2; e++) {
                    int c = nt * 8 + cbase + e;
                    if (c >= 66) {
                        S[nt][e] = -1e30f; S[nt][2 + e] = -1e30f;
                    } else if (c >= 2) {
                        int q = c - 2;
                        if (r0 >= 2 && r0 < 66)
                            S[nt][e]     += __half2float(Tb[(int)IdxT[(r0 - 2) * 64 + q] * 8 + h]);
                        if (r1 < 66)
                            S[nt][2 + e] += __half2float(Tb[(int)IdxT[(r1 - 2) * 64 + q] * 8 + h]);
                    }
                }
            }

            float m0 = -1e30f, m1 = -1e30f;
#pragma unroll
            for (int nt = 0; nt < 9; nt++) {
                m0 = fmaxf(m0, fmaxf(S[nt][0], S[nt][1]));
                m1 = fmaxf(m1, fmaxf(S[nt][2], S[nt][3]));
            }
            m0 = fmaxf(m0, __shfl_xor_sync(0xffffffffu, m0, 1));
            m0 = fmaxf(m0, __shfl_xor_sync(0xffffffffu, m0, 2));
            m1 = fmaxf(m1, __shfl_xor_sync(0xffffffffu, m1, 1));
            m1 = fmaxf(m1, __shfl_xor_sync(0xffffffffu, m1, 2));
            float s0 = 0.f, s1 = 0.f;
#pragma unroll
            for (int nt = 0; nt < 9; nt++) {
                S[nt][0] = __expf(S[nt][0] - m0); s0 += S[nt][0];
                S[nt][1] = __expf(S[nt][1] - m0); s0 += S[nt][1];
                S[nt][2] = __expf(S[nt][2] - m1); s1 += S[nt][2];
                S[nt][3] = __expf(S[nt][3] - m1); s1 += S[nt][3];
            }
            s0 += __shfl_xor_sync(0xffffffffu, s0, 1);
            s0 += __shfl_xor_sync(0xffffffffu, s0, 2);
            s1 += __shfl_xor_sync(0xffffffffu, s1, 1);
            s1 += __shfl_xor_sync(0xffffffffu, s1, 2);
            float inv0 = __frcp_rn(s0), inv1 = __frcp_rn(s1);

            uint32_t pa[5][4];
#pragma unroll
            for (int kt = 0; kt < 5; kt++) {
                int t0 = 2 * kt, t1 = 2 * kt + 1;
                pa[kt][0] = pk2(S[t0][0] * inv0, S[t0][1] * inv0);
                pa[kt][1] = pk2(S[t0][2] * inv1, S[t0][3] * inv1);
                if (t1 < 9) {
                    pa[kt][2] = pk2(S[t1][0] * inv0, S[t1][1] * inv0);
                    pa[kt][3] = pk2(S[t1][2] * inv1, S[t1][3] * inv1);
                } else {
                    pa[kt][2] = 0u; pa[kt][3] = 0u;
                }
            }

            float dO[4][4];
#pragma unroll
            for (int i = 0; i < 4; i++)
                dO[i][0] = dO[i][1] = dO[i][2] = dO[i][3] = 0.f;
            const __half* Bv = Vth + (lane & 15) * 88 + ((lane >> 4) * 8);
#pragma unroll
            for (int kt = 0; kt < 5; kt++) {
                uint32_t b0, b1, b2, b3;
                LDSM4(b0, b1, b2, b3, Bv + kt * 16);
                MMA16816(dO[0], pa[kt][0], pa[kt][1], pa[kt][2], pa[kt][3], b0, b2);
                MMA16816(dO[1], pa[kt][0], pa[kt][1], pa[kt][2], pa[kt][3], b1, b3);
                LDSM4(b0, b1, b2, b3, Bv + 16 * 88 + kt * 16);
                MMA16816(dO[2], pa[kt][0], pa[kt][1], pa[kt][2], pa[kt][3], b0, b2);
                MMA16816(dO[3], pa[kt][0], pa[kt][1], pa[kt][2], pa[kt][3], b1, b3);
            }
#pragma unroll
            for (int nt8 = 0; nt8 < 4; nt8++) {
                int c = h * 32 + nt8 * 8 + cbase;
                *(__half2*)(Os + r0 * 264 + c) = __floats2half2_rn(dO[nt8][0], dO[nt8][1]);
                *(__half2*)(Os + r1 * 264 + c) = __floats2half2_rn(dO[nt8][2], dO[nt8][3]);
            }
        } else {
            // warps 10-15: stage next weight pair (or proj chunk0 on last iter)
            int t0 = tid - 320;
            if (it < 3) stage_qkv_pair(it + 1, Wh, t0, 192);
            else        stage_wp(0, 192, Wh, t0, 192);
        }
        __syncthreads();
    }

    // ======== output projection: chunk0 = cols 0..191 (Wh), chunk1 staged ========
    if (warp < 12) {
        int job = warp;
        float acc[5][2][4];
#pragma unroll
        for (int i = 0; i < 5; i++)
#pragma unroll
            for (int j = 0; j < 2; j++)
                acc[i][j][0] = acc[i][j][1] = acc[i][j][2] = acc[i][j][3] = 0.f;
        const __half* Brow = Wh + (job * 16 + (lane & 15)) * 264 + ((lane >> 4) * 8);
        const __half* Arow = Os + (lane & 15) * 264 + ((lane >> 4) * 8);
#pragma unroll
        for (int ks = 0; ks < 16; ks++) {
            uint32_t b0, b1, b2, b3;
            LDSM4(b0, b1, b2, b3, Brow + ks * 16);
#pragma unroll
            for (int mt = 0; mt < 5; mt++) {
                uint32_t a0, a1, a2, a3;
                LDSM4(a0, a1, a2, a3, Arow + mt * 16 * 264 + ks * 16);
                MMA16816(acc[mt][0], a0, a1, a2, a3, b0, b2);
                MMA16816(acc[mt][1], a0, a1, a2, a3, b1, b3);
            }
        }
#pragma unroll
        for (int st = 0; st < 2; st++) {
            int cc = job * 16 + st * 8 + (lane & 3) * 2;
            float b0v = Bp[cc], b1v = Bp[cc + 1];
#pragma unroll
            for (int mt = 0; mt < 5; mt++) {
                int r0 = mt * 16 + (lane >> 2);
#pragma unroll
                for (int part = 0; part < 2; part++) {
                    int r = r0 + part * 8;
                    if (r < NTOK) {
                        float2 v;
                        v.x = acc[mt][st][part * 2 + 0] + b0v;
                        v.y = acc[mt][st][part * 2 + 1] + b1v;
                        *(float2*)(out + ((size_t)win * NTOK + r) * CDIM + cc) = v;
                    }
                }
            }
        }
    } else {
        stage_wp(192, 64, PB, tid - 384, 128);   // chunk1 into dead QKV region
    }
    __syncthreads();

    // chunk1: cols 192..255, 8 n8-column jobs
    if (warp < 8) {
        int n8 = warp;
        float acc[5][4];
#pragma unroll
        for (int i = 0; i < 5; i++)
            acc[i][0] = acc[i][1] = acc[i][2] = acc[i][3] = 0.f;
        const __half* Brow = PB + (n8 * 8 + (lane & 7)) * 264 + (((lane >> 3) & 1) * 8);
        const __half* Arow = Os + (lane & 15) * 264 + ((lane >> 4) * 8);
#pragma unroll
        for (int ks = 0; ks < 16; ks++) {
            uint32_t b0, b1;
            LDSM2(b0, b1, Brow + ks * 16);
#pragma unroll
            for (int mt = 0; mt < 5; mt++) {
                uint32_t a0, a1, a2, a3;
                LDSM4(a0, a1, a2, a3, Arow + mt * 16 * 264 + ks * 16);
                MMA16816(acc[mt], a0, a1, a2, a3, b0, b1);
            }
        }
        int cc = 192 + n8 * 8 + (lane & 3) * 2;
        float b0v = Bp[cc], b1v = Bp[cc + 1];
#pragma unroll
        for (int mt = 0; mt < 5; mt++) {
            int r0 = mt * 16 + (lane >> 2);
#pragma unroll
            for (int part = 0; part < 2; part++) {
                int r = r0 + part * 8;
                if (r < NTOK) {
                    float2 v;
                    v.x = acc[mt][part * 2 + 0] + b0v;
                    v.y = acc[mt][part * 2 + 1] + b1v;
                    *(float2*)(out + ((size_t)win * NTOK + r) * CDIM + cc) = v;
                }
            }
        }
    }
}

extern "C" void kernel_launch(void* const* d_in, const int* in_sizes, int n_in,
                              void* d_out, int out_size) {
    (void)in_sizes; (void)n_in; (void)out_size;
    const float* x      = (const float*)d_in[0];
    const float* qkv_w  = (const float*)d_in[1];
    const float* qkv_b  = (const float*)d_in[2];
    const float* tab    = (const float*)d_in[3];
    const float* proj_w = (const float*)d_in[4];
    const float* proj_b = (const float*)d_in[5];
    float* out = (float*)d_out;

    prep_kernel<<<768, 256>>>(qkv_w, proj_w);

    cudaFuncSetAttribute(win_attn_mma,
                         cudaFuncAttributeMaxDynamicSharedMemorySize, SMEM_BYTES);
    win_attn_mma<<<NWIN, NTHREADS, SMEM_BYTES>>>(
        x, qkv_b, tab, proj_b, out);
}